// round 1
// baseline (speedup 1.0000x reference)
#include <cuda_runtime.h>

#define FIN 128
#define HC  64
#define NH  4
#define CD  16
#define MAXN 50000

// ---------------- scratch (static device arrays; no allocation) ----------------
__device__ float  g_h1  [MAXN * HC];   // layer1 linear output [N,64]
__device__ float  g_s1s [MAXN * NH];   // per-node src attention logits [N,4]
__device__ float  g_s1d [MAXN * NH];
__device__ float  g_den1[MAXN * NH];   // softmax denominators [N,4]
__device__ float  g_out1[MAXN * HC];   // unnormalized message sums [N,64]
__device__ float2 g_h2  [MAXN];        // layer2 linear output [N,2]
__device__ float  g_s2s [MAXN];
__device__ float  g_s2d [MAXN];
__device__ float4 g_out2[MAXN];        // {num0, num1, denom, pad}

__device__ __forceinline__ void red_add_v4(float* addr, float4 v) {
    asm volatile("red.global.add.v4.f32 [%0], {%1, %2, %3, %4};"
                 :: "l"(addr), "f"(v.x), "f"(v.y), "f"(v.z), "f"(v.w)
                 : "memory");
}

// ---------------- kernel 0: zero accumulators ----------------
__global__ void zero_kernel(int N) {
    int i = blockIdx.x * blockDim.x + threadIdx.x;
    if (i < N * HC) g_out1[i] = 0.0f;
    if (i < N * NH) g_den1[i] = 0.0f;
    if (i < N)      g_out2[i] = make_float4(0.f, 0.f, 0.f, 0.f);
}

// ---------------- kernel 1: GEMM  h1 = x @ W1   (smem-tiled, 4x4 reg tiles) ----------------
#define XS_STRIDE 132
__global__ __launch_bounds__(256) void gemm1_kernel(const float* __restrict__ x,
                                                    const float* __restrict__ W1, int N) {
    __shared__ float Ws[FIN * HC];          // 32 KB
    __shared__ float Xs[64 * XS_STRIDE];    // ~33 KB, padded stride to kill bank conflicts
    const int tid = threadIdx.x;
    const int n0  = blockIdx.x * 64;

    for (int i = tid * 4; i < FIN * HC; i += 1024)
        *(float4*)&Ws[i] = *(const float4*)&W1[i];
    for (int i = tid * 4; i < 64 * FIN; i += 1024) {
        int r = i >> 7, c = i & 127;
        float4 v = make_float4(0.f, 0.f, 0.f, 0.f);
        if (n0 + r < N) v = *(const float4*)&x[(n0 + r) * FIN + c];
        *(float4*)&Xs[r * XS_STRIDE + c] = v;
    }
    __syncthreads();

    const int tx = tid & 15, ty = tid >> 4;     // 16x16 thread grid -> 4 rows x 4 cols each
    float acc[4][4] = {};
    #pragma unroll 4
    for (int k = 0; k < FIN; k++) {
        float xr[4];
        #pragma unroll
        for (int i = 0; i < 4; i++) xr[i] = Xs[(ty * 4 + i) * XS_STRIDE + k];
        float4 wv = *(float4*)&Ws[k * HC + tx * 4];
        #pragma unroll
        for (int i = 0; i < 4; i++) {
            acc[i][0] += xr[i] * wv.x;
            acc[i][1] += xr[i] * wv.y;
            acc[i][2] += xr[i] * wv.z;
            acc[i][3] += xr[i] * wv.w;
        }
    }
    #pragma unroll
    for (int i = 0; i < 4; i++) {
        int n = n0 + ty * 4 + i;
        if (n < N)
            *(float4*)&g_h1[n * HC + tx * 4] =
                make_float4(acc[i][0], acc[i][1], acc[i][2], acc[i][3]);
    }
}

// ---------------- kernel 2: per-(node,head) attention logits ----------------
__global__ void s1_kernel(const float* __restrict__ a_src,
                          const float* __restrict__ a_dst, int N) {
    int idx = blockIdx.x * blockDim.x + threadIdx.x;
    if (idx >= N * NH) return;
    int n = idx >> 2, h = idx & 3;
    const float4* hp = (const float4*)&g_h1[n * HC + h * CD];
    const float4* as = (const float4*)&a_src[h * CD];
    const float4* ad = (const float4*)&a_dst[h * CD];
    float ss = 0.f, sd = 0.f;
    #pragma unroll
    for (int i = 0; i < 4; i++) {
        float4 hv = hp[i], a = as[i], d = ad[i];
        ss += hv.x * a.x + hv.y * a.y + hv.z * a.z + hv.w * a.w;
        sd += hv.x * d.x + hv.y * d.y + hv.z * d.z + hv.w * d.w;
    }
    g_s1s[idx] = ss;
    g_s1d[idx] = sd;
}

// ---------------- kernel 3: layer-1 edge pass (16 threads/edge) ----------------
// exp(e) used directly instead of exp(e - segment_max): mathematically identical
// after normalization, and |e| is O(10) here so no fp32 overflow risk.
__global__ void edge1_kernel(const int* __restrict__ src,
                             const int* __restrict__ dst, int E, int N) {
    long long t = (long long)blockIdx.x * blockDim.x + threadIdx.x;
    const int ET  = E + N;
    int  eid  = (int)(t >> 4);
    int  sl   = (int)(t & 15);
    bool valid = eid < ET;
    int  ec   = valid ? eid : ET - 1;

    int s, d;
    if (ec < E) { s = __ldg(&src[ec]); d = __ldg(&dst[ec]); }
    else        { s = d = ec - E; }           // self loop

    float ex = 0.f;
    if (sl < 4) {                              // lanes 0..3 own heads 0..3
        float e = g_s1s[s * 4 + sl] + g_s1d[d * 4 + sl];
        e = e > 0.f ? e : 0.2f * e;            // leaky_relu(0.2)
        ex = __expf(e);
        if (valid) atomicAdd(&g_den1[d * 4 + sl], ex);
    }
    int lane = threadIdx.x & 31;
    float exh = __shfl_sync(0xffffffffu, ex, (lane & 16) | (sl >> 2));

    float4 hv = *(const float4*)&g_h1[s * HC + sl * 4];
    if (valid) {
        red_add_v4(&g_out1[d * HC + sl * 4],
                   make_float4(hv.x * exh, hv.y * exh, hv.z * exh, hv.w * exh));
    }
}

// ---------------- kernel 4: normalize + bias + elu + layer-2 GEMM + s2 logits ----------------
__global__ void node2_kernel(const float* __restrict__ b1, const float* __restrict__ W2,
                             const float* __restrict__ a_src2, const float* __restrict__ a_dst2,
                             int N) {
    int w    = (blockIdx.x * blockDim.x + threadIdx.x) >> 5;
    int lane = threadIdx.x & 31;
    if (w >= N) return;
    int c1 = lane, c2 = lane + 32;

    float v1 = g_out1[w * HC + c1] / g_den1[w * 4 + (c1 >> 4)] + b1[c1];
    float v2 = g_out1[w * HC + c2] / g_den1[w * 4 + (c2 >> 4)] + b1[c2];
    v1 = v1 > 0.f ? v1 : expm1f(v1);          // elu
    v2 = v2 > 0.f ? v2 : expm1f(v2);

    float a0 = v1 * W2[c1 * 2 + 0] + v2 * W2[c2 * 2 + 0];
    float a1 = v1 * W2[c1 * 2 + 1] + v2 * W2[c2 * 2 + 1];
    #pragma unroll
    for (int o = 16; o; o >>= 1) {
        a0 += __shfl_xor_sync(0xffffffffu, a0, o);
        a1 += __shfl_xor_sync(0xffffffffu, a1, o);
    }
    if (lane == 0) {
        g_h2[w]  = make_float2(a0, a1);
        g_s2s[w] = a0 * a_src2[0] + a1 * a_src2[1];
        g_s2d[w] = a0 * a_dst2[0] + a1 * a_dst2[1];
    }
}

// ---------------- kernel 5: layer-2 edge pass (1 thread/edge, single v4 RED) ----------------
__global__ void edge2_kernel(const int* __restrict__ src,
                             const int* __restrict__ dst, int E, int N) {
    int eid = blockIdx.x * blockDim.x + threadIdx.x;
    int ET  = E + N;
    if (eid >= ET) return;
    int s, d;
    if (eid < E) { s = __ldg(&src[eid]); d = __ldg(&dst[eid]); }
    else         { s = d = eid - E; }

    float e = g_s2s[s] + g_s2d[d];
    e = e > 0.f ? e : 0.2f * e;
    float ex = __expf(e);
    float2 h2 = g_h2[s];
    red_add_v4((float*)&g_out2[d], make_float4(h2.x * ex, h2.y * ex, ex, 0.f));
}

// ---------------- kernel 6: normalize + bias + log_softmax ----------------
__global__ void final_kernel(const float* __restrict__ b2, float* __restrict__ out, int N) {
    int n = blockIdx.x * blockDim.x + threadIdx.x;
    if (n >= N) return;
    float4 o = g_out2[n];
    float o0 = o.x / o.z + b2[0];
    float o1 = o.y / o.z + b2[1];
    float mx = fmaxf(o0, o1);
    float l  = mx + logf(expf(o0 - mx) + expf(o1 - mx));
    out[n * 2 + 0] = o0 - l;
    out[n * 2 + 1] = o1 - l;
}

// ---------------- launch ----------------
extern "C" void kernel_launch(void* const* d_in, const int* in_sizes, int n_in,
                              void* d_out, int out_size) {
    const float* x   = (const float*)d_in[0];
    const int*   ei  = (const int*)  d_in[1];
    const float* W1  = (const float*)d_in[2];
    const float* as1 = (const float*)d_in[3];
    const float* ad1 = (const float*)d_in[4];
    const float* b1  = (const float*)d_in[5];
    const float* W2  = (const float*)d_in[6];
    const float* as2 = (const float*)d_in[7];
    const float* ad2 = (const float*)d_in[8];
    const float* b2  = (const float*)d_in[9];

    int N = in_sizes[0] / FIN;
    int E = in_sizes[1] / 2;
    const int* src = ei;
    const int* dst = ei + E;
    float* out = (float*)d_out;

    zero_kernel <<<(N * HC + 255) / 256, 256>>>(N);
    gemm1_kernel<<<(N + 63) / 64, 256>>>(x, W1, N);
    s1_kernel   <<<(N * NH + 255) / 256, 256>>>(as1, ad1, N);

    long long T1 = (long long)(E + N) * 16;
    edge1_kernel<<<(unsigned)((T1 + 255) / 256), 256>>>(src, dst, E, N);

    node2_kernel<<<(N * 32 + 255) / 256, 256>>>(b1, W2, as2, ad2, N);
    edge2_kernel<<<(E + N + 255) / 256, 256>>>(src, dst, E, N);
    final_kernel<<<(N + 255) / 256, 256>>>(b2, out, N);
}

// round 2
// speedup vs baseline: 1.2084x; 1.2084x over previous
#include <cuda_runtime.h>
#include <cuda_fp16.h>

#define FIN 128
#define HC  64
#define NH  4
#define MAXN 50048
#define MAXE 1605632

// ---------------- static scratch ----------------
__device__ __half  g_h1h[MAXN * HC];    // layer1 features, fp16 (message payload)
__device__ float   g_s1s[MAXN * NH];    // per-node src logits [N,4]
__device__ float   g_s1d[MAXN * NH];
__device__ float2  g_h2 [MAXN];         // layer2 linear output
__device__ float   g_s2s[MAXN];
__device__ float   g_s2d[MAXN];
__device__ int     g_deg[MAXN];
__device__ int     g_off[MAXN];
__device__ int     g_cur[MAXN];
__device__ int     g_csr[MAXE];
__device__ int     g_bsum[64];

// ---------------- CSR build ----------------
__global__ void zero_deg_kernel(int N) {
    int i = blockIdx.x * blockDim.x + threadIdx.x;
    if (i < N) g_deg[i] = 0;
}

__global__ void hist_kernel(const int* __restrict__ dst, int E) {
    int e = blockIdx.x * blockDim.x + threadIdx.x;
    if (e < E) atomicAdd(&g_deg[dst[e]], 1);
}

// block-wise exclusive scan of g_deg into g_off (partial), block totals to g_bsum
__global__ __launch_bounds__(1024) void scan1_kernel(int N) {
    __shared__ int wsum[32];
    int i = blockIdx.x * 1024 + threadIdx.x;
    int v = (i < N) ? g_deg[i] : 0;
    int lane = threadIdx.x & 31, wid = threadIdx.x >> 5;
    int inc = v;
    #pragma unroll
    for (int o = 1; o < 32; o <<= 1) {
        int t = __shfl_up_sync(0xffffffffu, inc, o);
        if (lane >= o) inc += t;
    }
    if (lane == 31) wsum[wid] = inc;
    __syncthreads();
    if (wid == 0) {
        int s = wsum[lane];
        int si = s;
        #pragma unroll
        for (int o = 1; o < 32; o <<= 1) {
            int t = __shfl_up_sync(0xffffffffu, si, o);
            if (lane >= o) si += t;
        }
        wsum[lane] = si - s;                 // exclusive warp base
        if (lane == 31) g_bsum[blockIdx.x] = si;
    }
    __syncthreads();
    if (i < N) g_off[i] = inc - v + wsum[wid];
}

// scan the (<=64) block totals; 1 block of 32 threads
__global__ void scan2_kernel(int NB) {
    int lane = threadIdx.x;
    int a = (2 * lane     < NB) ? g_bsum[2 * lane]     : 0;
    int b = (2 * lane + 1 < NB) ? g_bsum[2 * lane + 1] : 0;
    int s = a + b, inc = s;
    #pragma unroll
    for (int o = 1; o < 32; o <<= 1) {
        int t = __shfl_up_sync(0xffffffffu, inc, o);
        if (lane >= o) inc += t;
    }
    int excl = inc - s;
    if (2 * lane     < NB) g_bsum[2 * lane]     = excl;
    if (2 * lane + 1 < NB) g_bsum[2 * lane + 1] = excl + a;
}

__global__ void scan3_kernel(int N) {
    int i = blockIdx.x * blockDim.x + threadIdx.x;
    if (i < N) {
        int o = g_off[i] + g_bsum[i >> 10];
        g_off[i] = o;
        g_cur[i] = o;
    }
}

__global__ void scatter_kernel(const int* __restrict__ src,
                               const int* __restrict__ dst, int E) {
    int e = blockIdx.x * blockDim.x + threadIdx.x;
    if (e >= E) return;
    int d   = dst[e];
    int idx = atomicAdd(&g_cur[d], 1);
    g_csr[idx] = src[e];
}

// ---------------- GEMM h1 = x @ W1, fused: fp16 store + s1 logits ----------------
#define XS_STRIDE 132
__global__ __launch_bounds__(256) void gemm1_kernel(const float* __restrict__ x,
                                                    const float* __restrict__ W1,
                                                    const float* __restrict__ as1,
                                                    const float* __restrict__ ad1, int N) {
    __shared__ float Ws[FIN * HC];
    __shared__ float Xs[64 * XS_STRIDE];
    const int tid = threadIdx.x;
    const int n0  = blockIdx.x * 64;

    for (int i = tid * 4; i < FIN * HC; i += 1024)
        *(float4*)&Ws[i] = *(const float4*)&W1[i];
    for (int i = tid * 4; i < 64 * FIN; i += 1024) {
        int r = i >> 7, c = i & 127;
        float4 v = make_float4(0.f, 0.f, 0.f, 0.f);
        if (n0 + r < N) v = *(const float4*)&x[(n0 + r) * FIN + c];
        *(float4*)&Xs[r * XS_STRIDE + c] = v;
    }
    __syncthreads();

    const int tx = tid & 15, ty = tid >> 4;
    float acc[4][4] = {};
    #pragma unroll 4
    for (int k = 0; k < FIN; k++) {
        float xr[4];
        #pragma unroll
        for (int i = 0; i < 4; i++) xr[i] = Xs[(ty * 4 + i) * XS_STRIDE + k];
        float4 wv = *(float4*)&Ws[k * HC + tx * 4];
        #pragma unroll
        for (int i = 0; i < 4; i++) {
            acc[i][0] += xr[i] * wv.x;
            acc[i][1] += xr[i] * wv.y;
            acc[i][2] += xr[i] * wv.z;
            acc[i][3] += xr[i] * wv.w;
        }
    }

    // epilogue: fp16 store + per-head attention logits (reduce over tx&3)
    const int head = tx >> 2;
    float4 aS = *(const float4*)&as1[head * 16 + (tx & 3) * 4];
    float4 aD = *(const float4*)&ad1[head * 16 + (tx & 3) * 4];
    #pragma unroll
    for (int i = 0; i < 4; i++) {
        int n = n0 + ty * 4 + i;
        if (n < N) {
            __half2 p0 = __floats2half2_rn(acc[i][0], acc[i][1]);
            __half2 p1 = __floats2half2_rn(acc[i][2], acc[i][3]);
            uint2 u;
            u.x = *(unsigned*)&p0;
            u.y = *(unsigned*)&p1;
            *(uint2*)(g_h1h + n * HC + tx * 4) = u;
        }
        float ps = acc[i][0]*aS.x + acc[i][1]*aS.y + acc[i][2]*aS.z + acc[i][3]*aS.w;
        float pd = acc[i][0]*aD.x + acc[i][1]*aD.y + acc[i][2]*aD.z + acc[i][3]*aD.w;
        ps += __shfl_xor_sync(0xffffffffu, ps, 1);
        ps += __shfl_xor_sync(0xffffffffu, ps, 2);
        pd += __shfl_xor_sync(0xffffffffu, pd, 1);
        pd += __shfl_xor_sync(0xffffffffu, pd, 2);
        if (n < N && (tx & 3) == 0) {
            g_s1s[n * 4 + head] = ps;
            g_s1d[n * 4 + head] = pd;
        }
    }
}

// ---------------- layer1 gather + fused normalize/elu/W2/s2 ----------------
// one warp per dst node; two 16-lane groups, one edge each per step.
// virtual edge list = CSR in-edges + one self loop (index == deg).
__global__ __launch_bounds__(256) void gather1_kernel(const float* __restrict__ b1,
                                                      const float* __restrict__ W2,
                                                      const float* __restrict__ as2,
                                                      const float* __restrict__ ad2, int N) {
    int w = (int)((blockIdx.x * (unsigned)blockDim.x + threadIdx.x) >> 5);
    int lane = threadIdx.x & 31;
    if (w >= N) return;
    const int g  = lane >> 4, sl = lane & 15;
    const unsigned gmask = g ? 0xFFFF0000u : 0x0000FFFFu;
    const int beg = g_off[w];
    const int deg = g_deg[w];
    float sd = (sl < 4) ? g_s1d[w * 4 + sl] : 0.f;

    float acc0 = 0.f, acc1 = 0.f, acc2 = 0.f, acc3 = 0.f, den = 0.f;

    int i = g;
    int s_nxt = 0;
    if (i <= deg) s_nxt = (i < deg) ? __ldg(&g_csr[beg + i]) : w;
    while (i <= deg) {
        int s  = s_nxt;
        int i2 = i + 2;
        if (i2 <= deg) s_nxt = (i2 < deg) ? __ldg(&g_csr[beg + i2]) : w;

        float ex = 0.f;
        if (sl < 4) {
            float e = __ldg(&g_s1s[s * 4 + sl]) + sd;
            e  = e > 0.f ? e : 0.2f * e;      // leaky_relu(0.2)
            ex = __expf(e);
            den += ex;
        }
        uint2 hv = *(const uint2*)(g_h1h + s * HC + sl * 4);
        float exh = __shfl_sync(gmask, ex, (g << 4) | (sl >> 2));
        float2 f0 = __half22float2(*(__half2*)&hv.x);
        float2 f1 = __half22float2(*(__half2*)&hv.y);
        acc0 += f0.x * exh; acc1 += f0.y * exh;
        acc2 += f1.x * exh; acc3 += f1.y * exh;
        i = i2;
    }
    __syncwarp();
    acc0 += __shfl_xor_sync(0xffffffffu, acc0, 16);
    acc1 += __shfl_xor_sync(0xffffffffu, acc1, 16);
    acc2 += __shfl_xor_sync(0xffffffffu, acc2, 16);
    acc3 += __shfl_xor_sync(0xffffffffu, acc3, 16);
    den  += __shfl_xor_sync(0xffffffffu, den, 16);
    float denL = __shfl_sync(0xffffffffu, den, sl >> 2);

    float a0 = 0.f, a1 = 0.f;
    if (g == 0) {
        int c = sl * 4;
        float v0 = acc0 / denL + b1[c + 0];
        float v1 = acc1 / denL + b1[c + 1];
        float v2 = acc2 / denL + b1[c + 2];
        float v3 = acc3 / denL + b1[c + 3];
        v0 = v0 > 0.f ? v0 : expm1f(v0);
        v1 = v1 > 0.f ? v1 : expm1f(v1);
        v2 = v2 > 0.f ? v2 : expm1f(v2);
        v3 = v3 > 0.f ? v3 : expm1f(v3);
        a0 = v0*W2[(c+0)*2]   + v1*W2[(c+1)*2]   + v2*W2[(c+2)*2]   + v3*W2[(c+3)*2];
        a1 = v0*W2[(c+0)*2+1] + v1*W2[(c+1)*2+1] + v2*W2[(c+2)*2+1] + v3*W2[(c+3)*2+1];
    }
    #pragma unroll
    for (int o = 8; o; o >>= 1) {
        a0 += __shfl_xor_sync(0xffffffffu, a0, o);
        a1 += __shfl_xor_sync(0xffffffffu, a1, o);
    }
    if (lane == 0) {
        g_h2[w]  = make_float2(a0, a1);
        g_s2s[w] = a0 * as2[0] + a1 * as2[1];
        g_s2d[w] = a0 * ad2[0] + a1 * ad2[1];
    }
}

// ---------------- layer2 gather + fused log_softmax ----------------
__global__ __launch_bounds__(256) void gather2_kernel(const float* __restrict__ b2,
                                                      float* __restrict__ out, int N) {
    int w = (int)((blockIdx.x * (unsigned)blockDim.x + threadIdx.x) >> 5);
    int lane = threadIdx.x & 31;
    if (w >= N) return;
    const int beg = g_off[w];
    const int deg = g_deg[w];
    float sd = g_s2d[w];

    float n0 = 0.f, n1 = 0.f, den = 0.f;
    for (int i = lane; i < deg; i += 32) {
        int s = __ldg(&g_csr[beg + i]);
        float e = __ldg(&g_s2s[s]) + sd;
        e = e > 0.f ? e : 0.2f * e;
        float ex = __expf(e);
        float2 h = g_h2[s];
        n0 += ex * h.x; n1 += ex * h.y; den += ex;
    }
    if (lane == 0) {   // self loop
        float e = g_s2s[w] + sd;
        e = e > 0.f ? e : 0.2f * e;
        float ex = __expf(e);
        float2 h = g_h2[w];
        n0 += ex * h.x; n1 += ex * h.y; den += ex;
    }
    #pragma unroll
    for (int o = 16; o; o >>= 1) {
        n0  += __shfl_xor_sync(0xffffffffu, n0, o);
        n1  += __shfl_xor_sync(0xffffffffu, n1, o);
        den += __shfl_xor_sync(0xffffffffu, den, o);
    }
    if (lane == 0) {
        float o0 = n0 / den + b2[0];
        float o1 = n1 / den + b2[1];
        float mx = fmaxf(o0, o1);
        float l  = mx + logf(expf(o0 - mx) + expf(o1 - mx));
        out[2 * w]     = o0 - l;
        out[2 * w + 1] = o1 - l;
    }
}

// ---------------- launch ----------------
extern "C" void kernel_launch(void* const* d_in, const int* in_sizes, int n_in,
                              void* d_out, int out_size) {
    const float* x   = (const float*)d_in[0];
    const int*   ei  = (const int*)  d_in[1];
    const float* W1  = (const float*)d_in[2];
    const float* as1 = (const float*)d_in[3];
    const float* ad1 = (const float*)d_in[4];
    const float* b1  = (const float*)d_in[5];
    const float* W2  = (const float*)d_in[6];
    const float* as2 = (const float*)d_in[7];
    const float* ad2 = (const float*)d_in[8];
    const float* b2  = (const float*)d_in[9];

    int N = in_sizes[0] / FIN;
    int E = in_sizes[1] / 2;
    const int* src = ei;
    const int* dst = ei + E;
    float* out = (float*)d_out;

    int NB = (N + 1023) / 1024;

    zero_deg_kernel<<<(N + 255) / 256, 256>>>(N);
    hist_kernel    <<<(E + 255) / 256, 256>>>(dst, E);
    scan1_kernel   <<<NB, 1024>>>(N);
    scan2_kernel   <<<1, 32>>>(NB);
    scan3_kernel   <<<(N + 255) / 256, 256>>>(N);
    scatter_kernel <<<(E + 255) / 256, 256>>>(src, dst, E);

    gemm1_kernel   <<<(N + 63) / 64, 256>>>(x, W1, as1, ad1, N);

    gather1_kernel <<<(N * 32 + 255) / 256, 256>>>(b1, W2, as2, ad2, N);
    gather2_kernel <<<(N * 32 + 255) / 256, 256>>>(b2, out, N);
}

// round 3
// speedup vs baseline: 1.3322x; 1.1024x over previous
#include <cuda_runtime.h>
#include <cuda_fp16.h>

#define FIN 128
#define HC  64
#define NH  4
#define MAXN 50048
#define MAXE 1605632

// ---------------- static scratch ----------------
__device__ __align__(16) __half g_h1h[MAXN * HC];  // layer1 features fp16 [N,64]
__device__ float   g_s1s[MAXN * NH];    // per-node src logits [N,4]
__device__ float   g_s1d[MAXN * NH];
__device__ float4  g_rec[MAXN];         // {h2.x, h2.y, s2_src, s2_dst}
__device__ int     g_deg[MAXN];
__device__ int     g_off[MAXN];
__device__ int     g_cur[MAXN];
__device__ int     g_csr[MAXE];
__device__ volatile unsigned g_word[64];   // lookback: flag(2b)<<30 | value

// ---------------- kernel: zero degree histogram + scan flags ----------------
__global__ void zero_kernel(int N) {
    int i = blockIdx.x * blockDim.x + threadIdx.x;
    if (i < N)  g_deg[i] = 0;
    if (i < 64) *(unsigned*)&g_word[i] = 0u;
}

__global__ void hist_kernel(const int* __restrict__ dst, int E) {
    int e = blockIdx.x * blockDim.x + threadIdx.x;
    if (e < E) atomicAdd(&g_deg[dst[e]], 1);
}

// ---------------- single-pass exclusive scan (decoupled lookback) ----------------
__global__ __launch_bounds__(1024) void scan_kernel(int N) {
    __shared__ int wsum[32];
    __shared__ int s_prefix;
    const int bid  = blockIdx.x;
    const int tid  = threadIdx.x;
    const int lane = tid & 31, wid = tid >> 5;
    const int i    = bid * 1024 + tid;

    int v   = (i < N) ? g_deg[i] : 0;
    int inc = v;
    #pragma unroll
    for (int o = 1; o < 32; o <<= 1) {
        int t = __shfl_up_sync(0xffffffffu, inc, o);
        if (lane >= o) inc += t;
    }
    if (lane == 31) wsum[wid] = inc;
    __syncthreads();

    if (wid == 0) {
        int s  = wsum[lane];
        int si = s;
        #pragma unroll
        for (int o = 1; o < 32; o <<= 1) {
            int t = __shfl_up_sync(0xffffffffu, si, o);
            if (lane >= o) si += t;
        }
        wsum[lane] = si - s;                       // exclusive warp base
        int total = __shfl_sync(0xffffffffu, si, 31);

        if (bid == 0) {
            if (lane == 0) {
                atomicExch((unsigned*)&g_word[0], (2u << 30) | (unsigned)total);
                s_prefix = 0;
            }
        } else {
            if (lane == 0)
                atomicExch((unsigned*)&g_word[bid], (1u << 30) | (unsigned)total);
            // lookback: warp scans predecessors, 32 at a time
            int running = 0;
            int base = bid - 1;
            while (true) {
                int idx = base - lane;
                unsigned wv;
                if (idx >= 0) {
                    do { wv = g_word[idx]; } while ((wv >> 30) == 0u);
                } else {
                    wv = 2u << 30;                 // virtual prefix 0
                }
                unsigned fl  = wv >> 30;
                int      val = (int)(wv & 0x3FFFFFFFu);
                unsigned pm  = __ballot_sync(0xffffffffu, fl >= 2u);
                int fp = __ffs(pm) - 1;            // nearest lane with a prefix
                int contrib = (pm == 0u || lane <= fp) ? val : 0;
                #pragma unroll
                for (int o = 16; o; o >>= 1)
                    contrib += __shfl_xor_sync(0xffffffffu, contrib, o);
                running += contrib;
                if (pm) break;
                base -= 32;
            }
            if (lane == 0) {
                atomicExch((unsigned*)&g_word[bid],
                           (2u << 30) | (unsigned)(running + total));
                s_prefix = running;
            }
        }
    }
    __syncthreads();
    if (i < N) {
        int o = s_prefix + wsum[wid] + inc - v;
        g_off[i] = o;
        g_cur[i] = o;
    }
}

__global__ void scatter_kernel(const int* __restrict__ src,
                               const int* __restrict__ dst, int E) {
    int e = blockIdx.x * blockDim.x + threadIdx.x;
    if (e >= E) return;
    int d   = dst[e];
    int idx = atomicAdd(&g_cur[d], 1);
    g_csr[idx] = src[e];
}

// ---------------- GEMM h1 = x @ W1, fused: fp16 store + s1 logits ----------------
#define XS_STRIDE 132
__global__ __launch_bounds__(256) void gemm1_kernel(const float* __restrict__ x,
                                                    const float* __restrict__ W1,
                                                    const float* __restrict__ as1,
                                                    const float* __restrict__ ad1, int N) {
    __shared__ float Ws[FIN * HC];
    __shared__ float Xs[64 * XS_STRIDE];
    const int tid = threadIdx.x;
    const int n0  = blockIdx.x * 64;

    for (int i = tid * 4; i < FIN * HC; i += 1024)
        *(float4*)&Ws[i] = *(const float4*)&W1[i];
    for (int i = tid * 4; i < 64 * FIN; i += 1024) {
        int r = i >> 7, c = i & 127;
        float4 v = make_float4(0.f, 0.f, 0.f, 0.f);
        if (n0 + r < N) v = *(const float4*)&x[(n0 + r) * FIN + c];
        *(float4*)&Xs[r * XS_STRIDE + c] = v;
    }
    __syncthreads();

    const int tx = tid & 15, ty = tid >> 4;
    float acc[4][4] = {};
    #pragma unroll 4
    for (int k = 0; k < FIN; k++) {
        float xr[4];
        #pragma unroll
        for (int i = 0; i < 4; i++) xr[i] = Xs[(ty * 4 + i) * XS_STRIDE + k];
        float4 wv = *(float4*)&Ws[k * HC + tx * 4];
        #pragma unroll
        for (int i = 0; i < 4; i++) {
            acc[i][0] += xr[i] * wv.x;
            acc[i][1] += xr[i] * wv.y;
            acc[i][2] += xr[i] * wv.z;
            acc[i][3] += xr[i] * wv.w;
        }
    }

    const int head = tx >> 2;
    float4 aS = *(const float4*)&as1[head * 16 + (tx & 3) * 4];
    float4 aD = *(const float4*)&ad1[head * 16 + (tx & 3) * 4];
    #pragma unroll
    for (int i = 0; i < 4; i++) {
        int n = n0 + ty * 4 + i;
        if (n < N) {
            __half2 p0 = __floats2half2_rn(acc[i][0], acc[i][1]);
            __half2 p1 = __floats2half2_rn(acc[i][2], acc[i][3]);
            uint2 u;
            u.x = *(unsigned*)&p0;
            u.y = *(unsigned*)&p1;
            *(uint2*)(g_h1h + n * HC + tx * 4) = u;
        }
        float ps = acc[i][0]*aS.x + acc[i][1]*aS.y + acc[i][2]*aS.z + acc[i][3]*aS.w;
        float pd = acc[i][0]*aD.x + acc[i][1]*aD.y + acc[i][2]*aD.z + acc[i][3]*aD.w;
        ps += __shfl_xor_sync(0xffffffffu, ps, 1);
        ps += __shfl_xor_sync(0xffffffffu, ps, 2);
        pd += __shfl_xor_sync(0xffffffffu, pd, 1);
        pd += __shfl_xor_sync(0xffffffffu, pd, 2);
        if (n < N && (tx & 3) == 0) {
            g_s1s[n * 4 + head] = ps;
            g_s1d[n * 4 + head] = pd;
        }
    }
}

// ---------------- layer1 gather: 4 edges/iter, 8 lanes/edge, uint4 loads ----------------
// Fused epilogue: normalize + bias + elu + W2 (64->2) + layer2 attention logits.
__global__ __launch_bounds__(256) void gather1_kernel(const float* __restrict__ b1,
                                                      const float* __restrict__ W2,
                                                      const float* __restrict__ as2,
                                                      const float* __restrict__ ad2, int N) {
    int w    = (int)((blockIdx.x * (unsigned)blockDim.x + threadIdx.x) >> 5);
    int lane = threadIdx.x & 31;
    if (w >= N) return;
    const int g  = lane >> 3;        // edge slot 0..3
    const int sl = lane & 7;         // 8 channels each: channels sl*8..sl*8+7 (head = sl>>1)
    const int beg = g_off[w];
    const int deg = g_deg[w];
    const int Ktot = (deg + 4) >> 2; // uniform trip count (virtual edge i==deg is self-loop)
    const float sdH = (sl < 4) ? g_s1d[w * 4 + sl] : 0.f;

    float acc[8] = {};
    float den = 0.f;

    int i = g;
    int s_cur = (i < deg) ? __ldg(&g_csr[beg + i]) : w;
    for (int k = 0; k < Ktot; k++) {
        int inext = i + 4;
        int s_nxt = (inext < deg) ? __ldg(&g_csr[beg + inext]) : w;
        bool valid = (i <= deg);

        float ex = 0.f;
        if (valid && sl < 4) {
            float e = __ldg(&g_s1s[s_cur * 4 + sl]) + sdH;
            e  = e > 0.f ? e : 0.2f * e;           // leaky_relu(0.2)
            ex = __expf(e);
            den += ex;
        }
        uint4 hv = *(const uint4*)(g_h1h + s_cur * HC + sl * 8);
        float exh = __shfl_sync(0xffffffffu, ex, (lane & 24) | (sl >> 1));

        float2 f0 = __half22float2(*(__half2*)&hv.x);
        float2 f1 = __half22float2(*(__half2*)&hv.y);
        float2 f2 = __half22float2(*(__half2*)&hv.z);
        float2 f3 = __half22float2(*(__half2*)&hv.w);
        acc[0] += f0.x * exh; acc[1] += f0.y * exh;
        acc[2] += f1.x * exh; acc[3] += f1.y * exh;
        acc[4] += f2.x * exh; acc[5] += f2.y * exh;
        acc[6] += f3.x * exh; acc[7] += f3.y * exh;

        s_cur = s_nxt;
        i = inext;
    }

    // reduce across the 4 edge groups
    #pragma unroll
    for (int j = 0; j < 8; j++) {
        acc[j] += __shfl_xor_sync(0xffffffffu, acc[j], 8);
        acc[j] += __shfl_xor_sync(0xffffffffu, acc[j], 16);
    }
    den += __shfl_xor_sync(0xffffffffu, den, 8);
    den += __shfl_xor_sync(0xffffffffu, den, 16);
    float denC = __shfl_sync(0xffffffffu, den, (lane & 24) | (sl >> 1));

    // epilogue on lanes 0..7 (g==0): each owns channels lane*8..lane*8+7
    float a0 = 0.f, a1 = 0.f;
    if (lane < 8) {
        int c0 = lane * 8;
        #pragma unroll
        for (int j = 0; j < 8; j++) {
            float v = acc[j] / denC + __ldg(&b1[c0 + j]);
            v = v > 0.f ? v : expm1f(v);          // elu
            a0 += v * __ldg(&W2[(c0 + j) * 2]);
            a1 += v * __ldg(&W2[(c0 + j) * 2 + 1]);
        }
    }
    a0 += __shfl_xor_sync(0xffffffffu, a0, 1);
    a1 += __shfl_xor_sync(0xffffffffu, a1, 1);
    a0 += __shfl_xor_sync(0xffffffffu, a0, 2);
    a1 += __shfl_xor_sync(0xffffffffu, a1, 2);
    a0 += __shfl_xor_sync(0xffffffffu, a0, 4);
    a1 += __shfl_xor_sync(0xffffffffu, a1, 4);
    if (lane == 0) {
        g_rec[w] = make_float4(a0, a1,
                               a0 * as2[0] + a1 * as2[1],
                               a0 * ad2[0] + a1 * ad2[1]);
    }
}

// ---------------- layer2 gather + fused log_softmax (one float4 per edge) ----------------
__global__ __launch_bounds__(256) void gather2_kernel(const float* __restrict__ b2,
                                                      float* __restrict__ out, int N) {
    int w    = (int)((blockIdx.x * (unsigned)blockDim.x + threadIdx.x) >> 5);
    int lane = threadIdx.x & 31;
    if (w >= N) return;
    const int beg = g_off[w];
    const int deg = g_deg[w];
    float4 recw = g_rec[w];
    float sd = recw.w;

    float n0 = 0.f, n1 = 0.f, den = 0.f;
    for (int i = lane; i < deg; i += 32) {
        int s = __ldg(&g_csr[beg + i]);
        float4 r = __ldg(&g_rec[s]);
        float e = r.z + sd;
        e = e > 0.f ? e : 0.2f * e;
        float ex = __expf(e);
        n0 += ex * r.x; n1 += ex * r.y; den += ex;
    }
    if (lane == 0) {   // self loop
        float e = recw.z + sd;
        e = e > 0.f ? e : 0.2f * e;
        float ex = __expf(e);
        n0 += ex * recw.x; n1 += ex * recw.y; den += ex;
    }
    #pragma unroll
    for (int o = 16; o; o >>= 1) {
        n0  += __shfl_xor_sync(0xffffffffu, n0, o);
        n1  += __shfl_xor_sync(0xffffffffu, n1, o);
        den += __shfl_xor_sync(0xffffffffu, den, o);
    }
    if (lane == 0) {
        float o0 = n0 / den + b2[0];
        float o1 = n1 / den + b2[1];
        float mx = fmaxf(o0, o1);
        float l  = mx + logf(expf(o0 - mx) + expf(o1 - mx));
        out[2 * w]     = o0 - l;
        out[2 * w + 1] = o1 - l;
    }
}

// ---------------- launch ----------------
extern "C" void kernel_launch(void* const* d_in, const int* in_sizes, int n_in,
                              void* d_out, int out_size) {
    const float* x   = (const float*)d_in[0];
    const int*   ei  = (const int*)  d_in[1];
    const float* W1  = (const float*)d_in[2];
    const float* as1 = (const float*)d_in[3];
    const float* ad1 = (const float*)d_in[4];
    const float* b1  = (const float*)d_in[5];
    const float* W2  = (const float*)d_in[6];
    const float* as2 = (const float*)d_in[7];
    const float* ad2 = (const float*)d_in[8];
    const float* b2  = (const float*)d_in[9];

    int N = in_sizes[0] / FIN;
    int E = in_sizes[1] / 2;
    const int* src = ei;
    const int* dst = ei + E;
    float* out = (float*)d_out;

    int NB = (N + 1023) / 1024;

    zero_kernel   <<<(N + 255) / 256, 256>>>(N);
    hist_kernel   <<<(E + 255) / 256, 256>>>(dst, E);
    scan_kernel   <<<NB, 1024>>>(N);
    scatter_kernel<<<(E + 255) / 256, 256>>>(src, dst, E);

    gemm1_kernel  <<<(N + 63) / 64, 256>>>(x, W1, as1, ad1, N);

    gather1_kernel<<<(N * 32 + 255) / 256, 256>>>(b1, W2, as2, ad2, N);
    gather2_kernel<<<(N * 32 + 255) / 256, 256>>>(b2, out, N);
}

// round 5
// speedup vs baseline: 1.4336x; 1.0762x over previous
#include <cuda_runtime.h>
#include <cuda_fp16.h>

#define FIN 128
#define HC  64
#define NH  4
#define MAXN 50048
#define MAXE 1605632

// ---------------- static scratch ----------------
__device__ __align__(16) __half g_h1h[MAXN * HC];  // layer1 features fp16 [N,64]
__device__ float   g_s1s[MAXN * NH];    // per-node src logits [N,4]
__device__ float   g_s1d[MAXN * NH];
__device__ float4  g_rec[MAXN];         // {h2.x, h2.y, s2_src, s2_dst}
__device__ int     g_deg[MAXN];
__device__ int     g_off[MAXN];
__device__ int     g_cur[MAXN];
__device__ int     g_csr[MAXE];
__device__ volatile unsigned g_word[64];   // lookback: flag(2b)<<30 | value

// ---------------- kernel: zero degree histogram + scan flags ----------------
__global__ void zero_kernel(int N) {
    int i = blockIdx.x * blockDim.x + threadIdx.x;
    if (i < N)  g_deg[i] = 0;
    if (i < 64) *(unsigned*)&g_word[i] = 0u;
}

// 4 independent atomics per thread (strided quarters, coalesced loads).
// GUARD on t < Q: padding threads must not touch any edge (R4 bug: they
// re-counted edges in [Q, Q+pad) that other threads own as e1).
__global__ void hist_kernel(const int* __restrict__ dst, int E, int Q) {
    int t = blockIdx.x * blockDim.x + threadIdx.x;
    if (t >= Q) return;
    int e1 = t + Q, e2 = t + 2 * Q, e3 = t + 3 * Q;
    atomicAdd(&g_deg[__ldg(&dst[t])], 1);            // t < Q <= E always valid
    if (e1 < E) atomicAdd(&g_deg[__ldg(&dst[e1])], 1);
    if (e2 < E) atomicAdd(&g_deg[__ldg(&dst[e2])], 1);
    if (e3 < E) atomicAdd(&g_deg[__ldg(&dst[e3])], 1);
}

// ---------------- single-pass exclusive scan (decoupled lookback) ----------------
__global__ __launch_bounds__(1024) void scan_kernel(int N) {
    __shared__ int wsum[32];
    __shared__ int s_prefix;
    const int bid  = blockIdx.x;
    const int tid  = threadIdx.x;
    const int lane = tid & 31, wid = tid >> 5;
    const int i    = bid * 1024 + tid;

    int v   = (i < N) ? g_deg[i] : 0;
    int inc = v;
    #pragma unroll
    for (int o = 1; o < 32; o <<= 1) {
        int t = __shfl_up_sync(0xffffffffu, inc, o);
        if (lane >= o) inc += t;
    }
    if (lane == 31) wsum[wid] = inc;
    __syncthreads();

    if (wid == 0) {
        int s  = wsum[lane];
        int si = s;
        #pragma unroll
        for (int o = 1; o < 32; o <<= 1) {
            int t = __shfl_up_sync(0xffffffffu, si, o);
            if (lane >= o) si += t;
        }
        wsum[lane] = si - s;                       // exclusive warp base
        int total = __shfl_sync(0xffffffffu, si, 31);

        if (bid == 0) {
            if (lane == 0) {
                atomicExch((unsigned*)&g_word[0], (2u << 30) | (unsigned)total);
                s_prefix = 0;
            }
        } else {
            if (lane == 0)
                atomicExch((unsigned*)&g_word[bid], (1u << 30) | (unsigned)total);
            int running = 0;
            int base = bid - 1;
            while (true) {
                int idx = base - lane;
                unsigned wv;
                if (idx >= 0) {
                    do { wv = g_word[idx]; } while ((wv >> 30) == 0u);
                } else {
                    wv = 2u << 30;                 // virtual prefix 0
                }
                unsigned fl  = wv >> 30;
                int      val = (int)(wv & 0x3FFFFFFFu);
                unsigned pm  = __ballot_sync(0xffffffffu, fl >= 2u);
                int fp = __ffs(pm) - 1;
                int contrib = (pm == 0u || lane <= fp) ? val : 0;
                #pragma unroll
                for (int o = 16; o; o >>= 1)
                    contrib += __shfl_xor_sync(0xffffffffu, contrib, o);
                running += contrib;
                if (pm) break;
                base -= 32;
            }
            if (lane == 0) {
                atomicExch((unsigned*)&g_word[bid],
                           (2u << 30) | (unsigned)(running + total));
                s_prefix = running;
            }
        }
    }
    __syncthreads();
    if (i < N) {
        int o = s_prefix + wsum[wid] + inc - v;
        g_off[i] = o;
        g_cur[i] = o;
    }
}

// 2 independent edges per thread (strided halves). GUARD on t < H.
__global__ void scatter_kernel(const int* __restrict__ src,
                               const int* __restrict__ dst, int E, int H) {
    int t = blockIdx.x * blockDim.x + threadIdx.x;
    if (t >= H) return;
    int e1 = t + H;
    int d0 = __ldg(&dst[t]);
    int s0 = __ldg(&src[t]);
    int d1 = 0, s1 = 0;
    bool v1 = (e1 < E);
    if (v1) { d1 = __ldg(&dst[e1]); s1 = __ldg(&src[e1]); }
    int i0 = atomicAdd(&g_cur[d0], 1);
    int i1 = v1 ? atomicAdd(&g_cur[d1], 1) : 0;
    g_csr[i0] = s0;
    if (v1) g_csr[i1] = s1;
}

// ---------------- GEMM h1 = x @ W1, fused: fp16 store + s1 logits ----------------
#define XS_STRIDE 132
__global__ __launch_bounds__(256) void gemm1_kernel(const float* __restrict__ x,
                                                    const float* __restrict__ W1,
                                                    const float* __restrict__ as1,
                                                    const float* __restrict__ ad1, int N) {
    __shared__ float Ws[FIN * HC];
    __shared__ float Xs[64 * XS_STRIDE];
    const int tid = threadIdx.x;
    const int n0  = blockIdx.x * 64;

    for (int i = tid * 4; i < FIN * HC; i += 1024)
        *(float4*)&Ws[i] = *(const float4*)&W1[i];
    for (int i = tid * 4; i < 64 * FIN; i += 1024) {
        int r = i >> 7, c = i & 127;
        float4 v = make_float4(0.f, 0.f, 0.f, 0.f);
        if (n0 + r < N) v = *(const float4*)&x[(n0 + r) * FIN + c];
        *(float4*)&Xs[r * XS_STRIDE + c] = v;
    }
    __syncthreads();

    const int tx = tid & 15, ty = tid >> 4;
    float acc[4][4] = {};
    #pragma unroll 4
    for (int k = 0; k < FIN; k++) {
        float xr[4];
        #pragma unroll
        for (int i = 0; i < 4; i++) xr[i] = Xs[(ty * 4 + i) * XS_STRIDE + k];
        float4 wv = *(float4*)&Ws[k * HC + tx * 4];
        #pragma unroll
        for (int i = 0; i < 4; i++) {
            acc[i][0] += xr[i] * wv.x;
            acc[i][1] += xr[i] * wv.y;
            acc[i][2] += xr[i] * wv.z;
            acc[i][3] += xr[i] * wv.w;
        }
    }

    const int head = tx >> 2;
    float4 aS = *(const float4*)&as1[head * 16 + (tx & 3) * 4];
    float4 aD = *(const float4*)&ad1[head * 16 + (tx & 3) * 4];
    #pragma unroll
    for (int i = 0; i < 4; i++) {
        int n = n0 + ty * 4 + i;
        if (n < N) {
            __half2 p0 = __floats2half2_rn(acc[i][0], acc[i][1]);
            __half2 p1 = __floats2half2_rn(acc[i][2], acc[i][3]);
            uint2 u;
            u.x = *(unsigned*)&p0;
            u.y = *(unsigned*)&p1;
            *(uint2*)(g_h1h + n * HC + tx * 4) = u;
        }
        float ps = acc[i][0]*aS.x + acc[i][1]*aS.y + acc[i][2]*aS.z + acc[i][3]*aS.w;
        float pd = acc[i][0]*aD.x + acc[i][1]*aD.y + acc[i][2]*aD.z + acc[i][3]*aD.w;
        ps += __shfl_xor_sync(0xffffffffu, ps, 1);
        ps += __shfl_xor_sync(0xffffffffu, ps, 2);
        pd += __shfl_xor_sync(0xffffffffu, pd, 1);
        pd += __shfl_xor_sync(0xffffffffu, pd, 2);
        if (n < N && (tx & 3) == 0) {
            g_s1s[n * 4 + head] = ps;
            g_s1d[n * 4 + head] = pd;
        }
    }
}

// ---------------- layer1 gather: 4 edges/iter, 8 lanes/edge, uint4 loads ----------------
__global__ __launch_bounds__(256) void gather1_kernel(const float* __restrict__ b1,
                                                      const float* __restrict__ W2,
                                                      const float* __restrict__ as2,
                                                      const float* __restrict__ ad2, int N) {
    int w    = (int)((blockIdx.x * (unsigned)blockDim.x + threadIdx.x) >> 5);
    int lane = threadIdx.x & 31;
    if (w >= N) return;
    const int g  = lane >> 3;        // edge slot 0..3
    const int sl = lane & 7;         // 8 channels each (head = sl>>1 on lanes sl<4)
    const int beg = g_off[w];
    const int deg = g_deg[w];
    const int Ktot = (deg + 4) >> 2; // uniform trip count (virtual edge i==deg is self-loop)
    const float sdH = (sl < 4) ? g_s1d[w * 4 + sl] : 0.f;

    float acc[8] = {};
    float den = 0.f;

    int i = g;
    int s_cur = (i < deg) ? __ldg(&g_csr[beg + i]) : w;
    for (int k = 0; k < Ktot; k++) {
        int inext = i + 4;
        int s_nxt = (inext < deg) ? __ldg(&g_csr[beg + inext]) : w;
        bool valid = (i <= deg);

        float ex = 0.f;
        if (valid && sl < 4) {
            float e = __ldg(&g_s1s[s_cur * 4 + sl]) + sdH;
            e  = e > 0.f ? e : 0.2f * e;           // leaky_relu(0.2)
            ex = __expf(e);
            den += ex;
        }
        uint4 hv = *(const uint4*)(g_h1h + s_cur * HC + sl * 8);
        float exh = __shfl_sync(0xffffffffu, ex, (lane & 24) | (sl >> 1));

        float2 f0 = __half22float2(*(__half2*)&hv.x);
        float2 f1 = __half22float2(*(__half2*)&hv.y);
        float2 f2 = __half22float2(*(__half2*)&hv.z);
        float2 f3 = __half22float2(*(__half2*)&hv.w);
        acc[0] += f0.x * exh; acc[1] += f0.y * exh;
        acc[2] += f1.x * exh; acc[3] += f1.y * exh;
        acc[4] += f2.x * exh; acc[5] += f2.y * exh;
        acc[6] += f3.x * exh; acc[7] += f3.y * exh;

        s_cur = s_nxt;
        i = inext;
    }

    #pragma unroll
    for (int j = 0; j < 8; j++) {
        acc[j] += __shfl_xor_sync(0xffffffffu, acc[j], 8);
        acc[j] += __shfl_xor_sync(0xffffffffu, acc[j], 16);
    }
    den += __shfl_xor_sync(0xffffffffu, den, 8);
    den += __shfl_xor_sync(0xffffffffu, den, 16);
    float denC = __shfl_sync(0xffffffffu, den, (lane & 24) | (sl >> 1));

    float a0 = 0.f, a1 = 0.f;
    if (lane < 8) {
        int c0 = lane * 8;
        #pragma unroll
        for (int j = 0; j < 8; j++) {
            float v = acc[j] / denC + __ldg(&b1[c0 + j]);
            v = v > 0.f ? v : expm1f(v);          // elu
            a0 += v * __ldg(&W2[(c0 + j) * 2]);
            a1 += v * __ldg(&W2[(c0 + j) * 2 + 1]);
        }
    }
    a0 += __shfl_xor_sync(0xffffffffu, a0, 1);
    a1 += __shfl_xor_sync(0xffffffffu, a1, 1);
    a0 += __shfl_xor_sync(0xffffffffu, a0, 2);
    a1 += __shfl_xor_sync(0xffffffffu, a1, 2);
    a0 += __shfl_xor_sync(0xffffffffu, a0, 4);
    a1 += __shfl_xor_sync(0xffffffffu, a1, 4);
    if (lane == 0) {
        g_rec[w] = make_float4(a0, a1,
                               a0 * as2[0] + a1 * as2[1],
                               a0 * ad2[0] + a1 * ad2[1]);
    }
}

// ---------------- layer2 gather + fused log_softmax ----------------
__global__ __launch_bounds__(256) void gather2_kernel(const float* __restrict__ b2,
                                                      float* __restrict__ out, int N) {
    int w    = (int)((blockIdx.x * (unsigned)blockDim.x + threadIdx.x) >> 5);
    int lane = threadIdx.x & 31;
    if (w >= N) return;
    const int beg = g_off[w];
    const int deg = g_deg[w];
    float4 recw = g_rec[w];
    float sd = recw.w;

    float n0 = 0.f, n1 = 0.f, den = 0.f;
    for (int i = lane; i < deg; i += 32) {
        int s = __ldg(&g_csr[beg + i]);
        float4 r = __ldg(&g_rec[s]);
        float e = r.z + sd;
        e = e > 0.f ? e : 0.2f * e;
        float ex = __expf(e);
        n0 += ex * r.x; n1 += ex * r.y; den += ex;
    }
    if (lane == 0) {   // self loop
        float e = recw.z + sd;
        e = e > 0.f ? e : 0.2f * e;
        float ex = __expf(e);
        n0 += ex * recw.x; n1 += ex * recw.y; den += ex;
    }
    #pragma unroll
    for (int o = 16; o; o >>= 1) {
        n0  += __shfl_xor_sync(0xffffffffu, n0, o);
        n1  += __shfl_xor_sync(0xffffffffu, n1, o);
        den += __shfl_xor_sync(0xffffffffu, den, o);
    }
    if (lane == 0) {
        float o0 = n0 / den + b2[0];
        float o1 = n1 / den + b2[1];
        float mx = fmaxf(o0, o1);
        float l  = mx + logf(expf(o0 - mx) + expf(o1 - mx));
        out[2 * w]     = o0 - l;
        out[2 * w + 1] = o1 - l;
    }
}

// ---------------- launch: CSR build || gemm1 via fork-join capture ----------------
extern "C" void kernel_launch(void* const* d_in, const int* in_sizes, int n_in,
                              void* d_out, int out_size) {
    const float* x   = (const float*)d_in[0];
    const int*   ei  = (const int*)  d_in[1];
    const float* W1  = (const float*)d_in[2];
    const float* as1 = (const float*)d_in[3];
    const float* ad1 = (const float*)d_in[4];
    const float* b1  = (const float*)d_in[5];
    const float* W2  = (const float*)d_in[6];
    const float* as2 = (const float*)d_in[7];
    const float* ad2 = (const float*)d_in[8];
    const float* b2  = (const float*)d_in[9];

    int N = in_sizes[0] / FIN;
    int E = in_sizes[1] / 2;
    const int* src = ei;
    const int* dst = ei + E;
    float* out = (float*)d_out;

    int NB = (N + 1023) / 1024;
    int Q  = (E + 3) / 4;       // hist quarter stride
    int H  = (E + 1) / 2;       // scatter half stride

    // one-time host-side stream/event setup (no device allocation)
    static cudaStream_t s2 = []() {
        cudaStream_t s; cudaStreamCreateWithFlags(&s, cudaStreamNonBlocking); return s;
    }();
    static cudaEvent_t evF = []() {
        cudaEvent_t e; cudaEventCreateWithFlags(&e, cudaEventDisableTiming); return e;
    }();
    static cudaEvent_t evJ = []() {
        cudaEvent_t e; cudaEventCreateWithFlags(&e, cudaEventDisableTiming); return e;
    }();

    // fork: gemm1 on s2, CSR build on default stream (disjoint scratch)
    cudaEventRecord(evF, 0);
    cudaStreamWaitEvent(s2, evF, 0);
    gemm1_kernel<<<(N + 63) / 64, 256, 0, s2>>>(x, W1, as1, ad1, N);
    cudaEventRecord(evJ, s2);

    zero_kernel   <<<(N + 255) / 256, 256>>>(N);
    hist_kernel   <<<(Q + 255) / 256, 256>>>(dst, E, Q);
    scan_kernel   <<<NB, 1024>>>(N);
    scatter_kernel<<<(H + 255) / 256, 256>>>(src, dst, E, H);

    // join
    cudaStreamWaitEvent(0, evJ, 0);

    gather1_kernel<<<(N * 32 + 255) / 256, 256>>>(b1, W2, as2, ad2, N);
    gather2_kernel<<<(N * 32 + 255) / 256, 256>>>(b2, out, N);
}